// round 11
// baseline (speedup 1.0000x reference)
#include <cuda_runtime.h>

// ContinuousPositionBias for GB300 — round 11:
// scatter: round-5 logic + strength-reduced padded addressing (4 base ptrs, imm offsets).
// MLP: round-10 packed-h (frozen, 32.1us).
// Inputs: 0 glob_pos(1,32,4) f32 | 1 coords_table(2209,2) f32 | 2 rpi(unused)
//         3 W1(2,512) | 4 b1(512) | 5 W2(512,16) | 6 num_prefix_tokens(=1)
// Output: (32,16,577,577) f32

#define NT     2209
#define HEADS  16
#define DHID   512
#define BATCH  32
#define OW     577
#define PLANE  (OW*OW)    // 332929

__device__ float g_bias[BATCH * HEADS * NT];   // (b,h,t)

typedef unsigned long long u64;

__device__ __forceinline__ u64 fma2(u64 a, u64 b, u64 c) {
    u64 d;
    asm("fma.rn.f32x2 %0, %1, %2, %3;" : "=l"(d) : "l"(a), "l"(b), "l"(c));
    return d;
}
__device__ __forceinline__ u64 pack2(float x) {
    u64 d;
    asm("mov.b64 %0, {%1, %1};" : "=l"(d) : "f"(x));
    return d;
}
__device__ __forceinline__ u64 packxy(float x, float y) {
    u64 d;
    asm("mov.b64 %0, {%1, %2};" : "=l"(d) : "f"(x), "f"(y));
    return d;
}
__device__ __forceinline__ void unpack2(u64 v, float& lo, float& hi) {
    asm("mov.b64 {%0, %1}, %2;" : "=f"(lo), "=f"(hi) : "l"(v));
}

// ---------------------------------------------------------------------------
// Kernel A: bias = relu((ctab+pos) @ W1 + b1) @ W2  (round-10 packed-h, frozen)
// ---------------------------------------------------------------------------
__global__ __launch_bounds__(128) void mlp_kernel(
    const float* __restrict__ glob, const float* __restrict__ ctab,
    const float* __restrict__ W1,   const float* __restrict__ b1,
    const float* __restrict__ W2)
{
    __shared__ __align__(16) ulonglong2 w1a[DHID];      // (wx,wx | wy,wy)
    __shared__ __align__(16) u64        w1b[DHID];      // (wz,wz)
    __shared__ __align__(16) float      w2s[DHID * HEADS];

    const int tid = threadIdx.x;
    {
        const float4* src = (const float4*)W2;
        float4* dst = (float4*)w2s;
        #pragma unroll
        for (int k = tid; k < DHID * HEADS / 4; k += 128) dst[k] = src[k];
        for (int d = tid; d < DHID; d += 128) {
            const float wx = W1[d], wy = W1[DHID + d], wz = b1[d];
            ulonglong2 q;
            q.x = packxy(wx, wx);
            q.y = packxy(wy, wy);
            w1a[d] = q;
            w1b[d] = packxy(wz, wz);
        }
    }
    __syncthreads();

    const int b = blockIdx.y;
    const float g0 = glob[b*4+0], g1 = glob[b*4+1];
    const float g2 = glob[b*4+2], g3 = glob[b*4+3];
    float p0 = g2 / g0 * 8.0f;
    float p1 = g3 / g1 * 8.0f;
    p0 = copysignf(log2f(fabsf(p0) + 1.0f), p0) * (2.0f / 3.0f) - 1.0f;
    p1 = copysignf(log2f(fabsf(p1) + 1.0f), p1) * (2.0f / 3.0f) - 1.0f;

    const int t0 = blockIdx.x * 256 + tid;
    const int t1 = t0 + 128;
    const bool v0 = (t0 < NT), v1 = (t1 < NT);

    float a0 = 0.f, a1 = 0.f, c0 = 0.f, c1 = 0.f;
    if (v0) { a0 = ctab[2*t0] + p0; a1 = ctab[2*t0+1] + p1; }
    if (v1) { c0 = ctab[2*t1] + p0; c1 = ctab[2*t1+1] + p1; }

    const u64 x01 = packxy(a0, c0);
    const u64 y01 = packxy(a1, c1);

    u64 accA[8], accB[8];
    #pragma unroll
    for (int k = 0; k < 8; k++) { accA[k] = 0ull; accB[k] = 0ull; }

    const ulonglong2* __restrict__ w2q = (const ulonglong2*)w2s;

    #pragma unroll 2
    for (int d = 0; d < DHID; d++) {
        const ulonglong2 wxy = w1a[d];
        const u64        wz2 = w1b[d];
        const u64 hp = fma2(x01, wxy.x, fma2(y01, wxy.y, wz2));
        float hAraw, hBraw;
        unpack2(hp, hAraw, hBraw);
        const u64 hA2 = pack2(fmaxf(hAraw, 0.0f));
        const u64 hB2 = pack2(fmaxf(hBraw, 0.0f));

        const ulonglong2 q0 = w2q[d*4 + 0];
        const ulonglong2 q1 = w2q[d*4 + 1];
        const ulonglong2 q2 = w2q[d*4 + 2];
        const ulonglong2 q3 = w2q[d*4 + 3];
        accA[0] = fma2(hA2, q0.x, accA[0]);  accB[0] = fma2(hB2, q0.x, accB[0]);
        accA[1] = fma2(hA2, q0.y, accA[1]);  accB[1] = fma2(hB2, q0.y, accB[1]);
        accA[2] = fma2(hA2, q1.x, accA[2]);  accB[2] = fma2(hB2, q1.x, accB[2]);
        accA[3] = fma2(hA2, q1.y, accA[3]);  accB[3] = fma2(hB2, q1.y, accB[3]);
        accA[4] = fma2(hA2, q2.x, accA[4]);  accB[4] = fma2(hB2, q2.x, accB[4]);
        accA[5] = fma2(hA2, q2.y, accA[5]);  accB[5] = fma2(hB2, q2.y, accB[5]);
        accA[6] = fma2(hA2, q3.x, accA[6]);  accB[6] = fma2(hB2, q3.x, accB[6]);
        accA[7] = fma2(hA2, q3.y, accA[7]);  accB[7] = fma2(hB2, q3.y, accB[7]);
    }

    float* base = g_bias + (size_t)b * (HEADS * NT);
    if (v0) {
        #pragma unroll
        for (int k = 0; k < 8; k++) {
            float lo, hi; unpack2(accA[k], lo, hi);
            base[(2*k)   * NT + t0] = lo;
            base[(2*k+1) * NT + t0] = hi;
        }
    }
    if (v1) {
        #pragma unroll
        for (int k = 0; k < 8; k++) {
            float lo, hi; unpack2(accB[k], lo, hi);
            base[(2*k)   * NT + t1] = lo;
            base[(2*k+1) * NT + t1] = hi;
        }
    }
}

// ---------------------------------------------------------------------------
// Kernel B — diagonal-window scatter with strength-reduced padded addressing.
//   phys(A+k) = pA + k + floor((am+k)/4),  pA = A + (A>>2), am = A & 3.
//   floor((am+k)/4) over am in [0,3] is one of {E0=0, E1=(am>=1), E2=(am>=2),
//   E3=(am==3)} plus a constant -> 4 base pointers + immediate offsets.
// Window/select logic identical to round 5.
// ---------------------------------------------------------------------------
#define FRONT 32

__global__ __launch_bounds__(192) void scatter_kernel(float* __restrict__ out)
{
    __shared__ float sh[1536];
    const int tid   = threadIdx.x;
    const int ib    = blockIdx.x;     // 0..23 bands, 24 = zero-row writer
    const int plane = blockIdx.y;     // 0..511
    float* __restrict__ pb = out + (size_t)plane * PLANE;

    if (ib == 24) {                   // row 0 is all zeros
        for (int c = tid; c < OW; c += 192) pb[c] = 0.0f;
        return;
    }

    const float* __restrict__ bp = g_bias + (size_t)plane * NT + 47 * ib;
    for (int u = tid; u < 1128; u += 192) {
        int a = (1127 - u) + FRONT;
        sh[a + (a >> 2)] = bp[u];
    }
    __syncthreads();

    const int w     = tid >> 5;
    const int lane  = tid & 31;
    const int ii0   = 4 * w;
    const int r0    = 1 + 24 * ib + ii0;
    const int basev = 23 - ii0;
    const int alpha = (int)(((size_t)plane * PLANE + (size_t)r0 * OW) & 3);
    const int cs    = (4 - alpha) & 3;
    float* __restrict__ rp = pb + (size_t)r0 * OW;

    for (int t = 0; t < 5; t++) {
        const int k = lane + 32 * t;
        if (k > 144) continue;
        const int cbase = cs + 4 * k;

        if (cbase >= 4 && cbase <= 573) {
            const int j0 = cbase - 1;
            const int q0 = (j0 * 2731) >> 16;
            const int m0 = j0 - 24 * q0;
            const int A  = basev + j0 + 23 * q0 + FRONT;

            // base pointers with padding folded in
            const int pA = A + (A >> 2);
            const int am = A & 3;
            const int E1 = (am + 3) >> 2;   // am >= 1
            const int E2 = am >> 1;         // am >= 2
            const int E3 = (am + 1) >> 2;   // am == 3
            const float* __restrict__ B0p = sh + pA;
            const float* __restrict__ B1p = B0p + E1;
            const float* __restrict__ B2p = B0p + E2;
            const float* __restrict__ B3p = B0p + E3;

            float wv[10], wc5[5];
            wv[0] = B2p[-8]; wv[1] = B1p[-7]; wv[2] = B0p[-5]; wv[3] = B3p[-4];
            wv[4] = B2p[-3]; wv[5] = B1p[-2]; wv[6] = B0p[ 0]; wv[7] = B3p[ 1];
            wv[8] = B2p[ 2]; wv[9] = B1p[ 3];

            const bool bwd = (m0 <= 2);
            wc5[0] = *(bwd ? B1p - 37 : B2p + 27);
            wc5[1] = *(bwd ? B0p - 35 : B1p + 28);
            wc5[2] = *(bwd ? B3p - 34 : B0p + 30);
            wc5[3] = *(bwd ? B2p - 33 : B3p + 31);
            wc5[4] = *(bwd ? B1p - 32 : B2p + 32);

            #pragma unroll
            for (int di = 0; di < 4; di++) {
                float4 v;
                float* vv = (float*)&v;
                #pragma unroll
                for (int e = 0; e < 4; e++) {
                    const int x   = e - di;
                    const int idx = e - 2 * di + 6;
                    if (x > 0) {
                        vv[e] = (m0 >= 24 - x) ? wc5[idx - 5] : wv[idx];
                    } else if (x < 0) {
                        vv[e] = (m0 <  -x)     ? wc5[idx]     : wv[idx];
                    } else {
                        vv[e] = wv[idx];
                    }
                }
                *(float4*)(rp + di * OW + (cbase - di)) = v;
            }
        } else {
            #pragma unroll
            for (int di = 0; di < 4; di++) {
                int clo = (k == 0) ? 0 : (cbase - di);
                int chi = cbase - di + 3;
                if (chi > 576) chi = 576;
                for (int c = clo; c <= chi; c++) {
                    float val = 0.0f;
                    if (c >= 1) {
                        const int j = c - 1;
                        const int q = (j * 2731) >> 16;
                        const int a = basev - di + j + 23 * q + FRONT;
                        val = sh[a + (a >> 2)];
                    }
                    rp[di * OW + c] = val;
                }
            }
        }
    }
}

// ---------------------------------------------------------------------------
extern "C" void kernel_launch(void* const* d_in, const int* in_sizes, int n_in,
                              void* d_out, int out_size)
{
    const float* glob = (const float*)d_in[0];
    const float* ctab = (const float*)d_in[1];
    const float* W1   = (const float*)d_in[3];
    const float* b1   = (const float*)d_in[4];
    const float* W2   = (const float*)d_in[5];
    float* out        = (float*)d_out;

    mlp_kernel<<<dim3((NT + 255) / 256, BATCH), 128>>>(glob, ctab, W1, b1, W2);
    scatter_kernel<<<dim3(25, BATCH * HEADS), 192>>>(out);
}

// round 12
// speedup vs baseline: 1.6050x; 1.6050x over previous
#include <cuda_runtime.h>

// ContinuousPositionBias for GB300 — round 12:
// exact round-10 champion (147.5us) + streaming stores (__stcs) on all output writes.
// Inputs: 0 glob_pos(1,32,4) f32 | 1 coords_table(2209,2) f32 | 2 rpi(unused)
//         3 W1(2,512) | 4 b1(512) | 5 W2(512,16) | 6 num_prefix_tokens(=1)
// Output: (32,16,577,577) f32

#define NT     2209
#define HEADS  16
#define DHID   512
#define BATCH  32
#define OW     577
#define PLANE  (OW*OW)    // 332929

__device__ float g_bias[BATCH * HEADS * NT];   // (b,h,t)

typedef unsigned long long u64;

__device__ __forceinline__ u64 fma2(u64 a, u64 b, u64 c) {
    u64 d;
    asm("fma.rn.f32x2 %0, %1, %2, %3;" : "=l"(d) : "l"(a), "l"(b), "l"(c));
    return d;
}
__device__ __forceinline__ u64 pack2(float x) {
    u64 d;
    asm("mov.b64 %0, {%1, %1};" : "=l"(d) : "f"(x));
    return d;
}
__device__ __forceinline__ u64 packxy(float x, float y) {
    u64 d;
    asm("mov.b64 %0, {%1, %2};" : "=l"(d) : "f"(x), "f"(y));
    return d;
}
__device__ __forceinline__ void unpack2(u64 v, float& lo, float& hi) {
    asm("mov.b64 {%0, %1}, %2;" : "=f"(lo), "=f"(hi) : "l"(v));
}

// ---------------------------------------------------------------------------
// Kernel A: bias = relu((ctab+pos) @ W1 + b1) @ W2  (round-10 packed-h, frozen)
// ---------------------------------------------------------------------------
__global__ __launch_bounds__(128) void mlp_kernel(
    const float* __restrict__ glob, const float* __restrict__ ctab,
    const float* __restrict__ W1,   const float* __restrict__ b1,
    const float* __restrict__ W2)
{
    __shared__ __align__(16) ulonglong2 w1a[DHID];      // (wx,wx | wy,wy)
    __shared__ __align__(16) u64        w1b[DHID];      // (wz,wz)
    __shared__ __align__(16) float      w2s[DHID * HEADS];

    const int tid = threadIdx.x;
    {
        const float4* src = (const float4*)W2;
        float4* dst = (float4*)w2s;
        #pragma unroll
        for (int k = tid; k < DHID * HEADS / 4; k += 128) dst[k] = src[k];
        for (int d = tid; d < DHID; d += 128) {
            const float wx = W1[d], wy = W1[DHID + d], wz = b1[d];
            ulonglong2 q;
            q.x = packxy(wx, wx);
            q.y = packxy(wy, wy);
            w1a[d] = q;
            w1b[d] = packxy(wz, wz);
        }
    }
    __syncthreads();

    const int b = blockIdx.y;
    const float g0 = glob[b*4+0], g1 = glob[b*4+1];
    const float g2 = glob[b*4+2], g3 = glob[b*4+3];
    float p0 = g2 / g0 * 8.0f;
    float p1 = g3 / g1 * 8.0f;
    p0 = copysignf(log2f(fabsf(p0) + 1.0f), p0) * (2.0f / 3.0f) - 1.0f;
    p1 = copysignf(log2f(fabsf(p1) + 1.0f), p1) * (2.0f / 3.0f) - 1.0f;

    const int t0 = blockIdx.x * 256 + tid;
    const int t1 = t0 + 128;
    const bool v0 = (t0 < NT), v1 = (t1 < NT);

    float a0 = 0.f, a1 = 0.f, c0 = 0.f, c1 = 0.f;
    if (v0) { a0 = ctab[2*t0] + p0; a1 = ctab[2*t0+1] + p1; }
    if (v1) { c0 = ctab[2*t1] + p0; c1 = ctab[2*t1+1] + p1; }

    const u64 x01 = packxy(a0, c0);
    const u64 y01 = packxy(a1, c1);

    u64 accA[8], accB[8];
    #pragma unroll
    for (int k = 0; k < 8; k++) { accA[k] = 0ull; accB[k] = 0ull; }

    const ulonglong2* __restrict__ w2q = (const ulonglong2*)w2s;

    #pragma unroll 2
    for (int d = 0; d < DHID; d++) {
        const ulonglong2 wxy = w1a[d];
        const u64        wz2 = w1b[d];
        const u64 hp = fma2(x01, wxy.x, fma2(y01, wxy.y, wz2));
        float hAraw, hBraw;
        unpack2(hp, hAraw, hBraw);
        const u64 hA2 = pack2(fmaxf(hAraw, 0.0f));
        const u64 hB2 = pack2(fmaxf(hBraw, 0.0f));

        const ulonglong2 q0 = w2q[d*4 + 0];
        const ulonglong2 q1 = w2q[d*4 + 1];
        const ulonglong2 q2 = w2q[d*4 + 2];
        const ulonglong2 q3 = w2q[d*4 + 3];
        accA[0] = fma2(hA2, q0.x, accA[0]);  accB[0] = fma2(hB2, q0.x, accB[0]);
        accA[1] = fma2(hA2, q0.y, accA[1]);  accB[1] = fma2(hB2, q0.y, accB[1]);
        accA[2] = fma2(hA2, q1.x, accA[2]);  accB[2] = fma2(hB2, q1.x, accB[2]);
        accA[3] = fma2(hA2, q1.y, accA[3]);  accB[3] = fma2(hB2, q1.y, accB[3]);
        accA[4] = fma2(hA2, q2.x, accA[4]);  accB[4] = fma2(hB2, q2.x, accB[4]);
        accA[5] = fma2(hA2, q2.y, accA[5]);  accB[5] = fma2(hB2, q2.y, accB[5]);
        accA[6] = fma2(hA2, q3.x, accA[6]);  accB[6] = fma2(hB2, q3.x, accB[6]);
        accA[7] = fma2(hA2, q3.y, accA[7]);  accB[7] = fma2(hB2, q3.y, accB[7]);
    }

    float* base = g_bias + (size_t)b * (HEADS * NT);
    if (v0) {
        #pragma unroll
        for (int k = 0; k < 8; k++) {
            float lo, hi; unpack2(accA[k], lo, hi);
            base[(2*k)   * NT + t0] = lo;
            base[(2*k+1) * NT + t0] = hi;
        }
    }
    if (v1) {
        #pragma unroll
        for (int k = 0; k < 8; k++) {
            float lo, hi; unpack2(accB[k], lo, hi);
            base[(2*k)   * NT + t1] = lo;
            base[(2*k+1) * NT + t1] = hi;
        }
    }
}

// ---------------------------------------------------------------------------
// Kernel B — diagonal-window scatter (round-5 logic), streaming stores.
//   val(r=1+24ib+ii, c>=1) = rev[(23-ii) + f(c)],  f(c)=(c-1)+23*((c-1)/24)
// ---------------------------------------------------------------------------
#define FRONT 32

__global__ __launch_bounds__(192) void scatter_kernel(float* __restrict__ out)
{
    __shared__ float sh[1536];
    const int tid   = threadIdx.x;
    const int ib    = blockIdx.x;     // 0..23 bands, 24 = zero-row writer
    const int plane = blockIdx.y;     // 0..511
    float* __restrict__ pb = out + (size_t)plane * PLANE;

    if (ib == 24) {                   // row 0 is all zeros
        for (int c = tid; c < OW; c += 192) __stcs(pb + c, 0.0f);
        return;
    }

    const float* __restrict__ bp = g_bias + (size_t)plane * NT + 47 * ib;
    for (int u = tid; u < 1128; u += 192) {
        int a = (1127 - u) + FRONT;
        sh[a + (a >> 2)] = bp[u];
    }
    __syncthreads();

    const int w     = tid >> 5;
    const int lane  = tid & 31;
    const int ii0   = 4 * w;
    const int r0    = 1 + 24 * ib + ii0;
    const int basev = 23 - ii0;
    const int alpha = (int)(((size_t)plane * PLANE + (size_t)r0 * OW) & 3);
    const int cs    = (4 - alpha) & 3;
    float* __restrict__ rp = pb + (size_t)r0 * OW;

    for (int t = 0; t < 5; t++) {
        const int k = lane + 32 * t;
        if (k > 144) continue;
        const int cbase = cs + 4 * k;

        if (cbase >= 4 && cbase <= 573) {
            const int j0 = cbase - 1;
            const int q0 = (j0 * 2731) >> 16;
            const int m0 = j0 - 24 * q0;
            const int A  = basev + j0 + 23 * q0 + FRONT;

            float wv[10], wc5[5];
            {
                const int aW = A - 6;
                #pragma unroll
                for (int i = 0; i < 10; i++) { int a = aW + i; wv[i] = sh[a + (a >> 2)]; }
                const int aC = (m0 <= 2) ? (A - 29) : (A + 22);
                #pragma unroll
                for (int i = 0; i < 5; i++) { int a = aC + i; wc5[i] = sh[a + (a >> 2)]; }
            }

            #pragma unroll
            for (int di = 0; di < 4; di++) {
                float4 v;
                float* vv = (float*)&v;
                #pragma unroll
                for (int e = 0; e < 4; e++) {
                    const int x   = e - di;
                    const int idx = e - 2 * di + 6;
                    if (x > 0) {
                        vv[e] = (m0 >= 24 - x) ? wc5[idx - 5] : wv[idx];
                    } else if (x < 0) {
                        vv[e] = (m0 <  -x)     ? wc5[idx]     : wv[idx];
                    } else {
                        vv[e] = wv[idx];
                    }
                }
                __stcs((float4*)(rp + di * OW + (cbase - di)), v);
            }
        } else {
            #pragma unroll
            for (int di = 0; di < 4; di++) {
                int clo = (k == 0) ? 0 : (cbase - di);
                int chi = cbase - di + 3;
                if (chi > 576) chi = 576;
                for (int c = clo; c <= chi; c++) {
                    float val = 0.0f;
                    if (c >= 1) {
                        const int j = c - 1;
                        const int q = (j * 2731) >> 16;
                        const int a = basev - di + j + 23 * q + FRONT;
                        val = sh[a + (a >> 2)];
                    }
                    __stcs(rp + di * OW + c, val);
                }
            }
        }
    }
}

// ---------------------------------------------------------------------------
extern "C" void kernel_launch(void* const* d_in, const int* in_sizes, int n_in,
                              void* d_out, int out_size)
{
    const float* glob = (const float*)d_in[0];
    const float* ctab = (const float*)d_in[1];
    const float* W1   = (const float*)d_in[3];
    const float* b1   = (const float*)d_in[4];
    const float* W2   = (const float*)d_in[5];
    float* out        = (float*)d_out;

    mlp_kernel<<<dim3((NT + 255) / 256, BATCH), 128>>>(glob, ctab, W1, b1, W2);
    scatter_kernel<<<dim3(25, BATCH * HEADS), 192>>>(out);
}